// round 8
// baseline (speedup 1.0000x reference)
#include <cuda_runtime.h>
#include <cstdint>

// ----------------------------- problem constants -----------------------------
#define M_DIM 8192
#define N_DIM 4096
#define K_DIM 4096
#define FP8MAX 448.0f
#define EPSV 1e-12f

// ----------------------------- GEMM tiling ----------------------------------
#define BM 128
#define BN 128
#define BK 64                   // K bytes (fp8 elems) per stage
#define STAGES 6
#define KT (K_DIM / BK)         // 64 k-tiles

// per-stage smem: A[128][64B] + B[128][64B] = 16 KB
#define STG_BYTES 16384
#define B_OFF 8192
#define SMEM_BYTES (STAGES * STG_BYTES)   // 98304

// ----------------------------- scratch (static device mem) ------------------
__device__ __align__(256) uint8_t g_Xq[(size_t)M_DIM * K_DIM];
__device__ __align__(256) uint8_t g_Wq[(size_t)N_DIM * K_DIM];
__device__ __align__(16) float g_Xs[M_DIM];
__device__ __align__(16) float g_Ws[N_DIM];

// ----------------------------- PTX helpers ----------------------------------
__device__ __forceinline__ uint32_t smem_u32(const void* p) {
    uint32_t a;
    asm("{ .reg .u64 t; cvta.to.shared.u64 t, %1; cvt.u32.u64 %0, t; }"
        : "=r"(a) : "l"(p));
    return a;
}
__device__ __forceinline__ void cp16(uint32_t s, const void* g) {
    asm volatile("cp.async.cg.shared.global [%0], [%1], 16;" :: "r"(s), "l"(g));
}
__device__ __forceinline__ void cp_commit() {
    asm volatile("cp.async.commit_group;" ::: "memory");
}
template <int N>
__device__ __forceinline__ void cp_wait() {
    asm volatile("cp.async.wait_group %0;" :: "n"(N) : "memory");
}
__device__ __forceinline__ void ldsm4(uint32_t* r, uint32_t addr) {
    asm volatile("ldmatrix.sync.aligned.m8n8.x4.shared.b16 {%0,%1,%2,%3}, [%4];"
                 : "=r"(r[0]), "=r"(r[1]), "=r"(r[2]), "=r"(r[3]) : "r"(addr));
}
__device__ __forceinline__ void mma_fp8(float* d, const uint32_t* a,
                                        uint32_t b0, uint32_t b1) {
    asm volatile(
        "mma.sync.aligned.m16n8k32.row.col.f32.e4m3.e4m3.f32 "
        "{%0,%1,%2,%3}, {%4,%5,%6,%7}, {%8,%9}, {%0,%1,%2,%3};"
        : "+f"(d[0]), "+f"(d[1]), "+f"(d[2]), "+f"(d[3])
        : "r"(a[0]), "r"(a[1]), "r"(a[2]), "r"(a[3]), "r"(b0), "r"(b1));
}
// pack two f32 -> e4m3x2 (lo in low byte), RN + satfinite
__device__ __forceinline__ uint16_t cvt_e4m3x2(float lo, float hi) {
    uint16_t r;
    asm volatile("cvt.rn.satfinite.e4m3x2.f32 %0, %1, %2;" : "=h"(r) : "f"(hi), "f"(lo));
    return r;
}

// ----------------------------- weight quant ---------------------------------
__global__ void __launch_bounds__(256) wquant_kernel(const float* __restrict__ w) {
    const int row = blockIdx.x;
    const float4* wr = (const float4*)(w + (size_t)row * K_DIM);

    float4 v[4];
    float mx = 0.f;
#pragma unroll
    for (int i = 0; i < 4; i++) {
        v[i] = wr[threadIdx.x + i * 256];
        mx = fmaxf(mx, fmaxf(fmaxf(fabsf(v[i].x), fabsf(v[i].y)),
                             fmaxf(fabsf(v[i].z), fabsf(v[i].w))));
    }
    __shared__ float red[8];
    __shared__ float s_scale;
#pragma unroll
    for (int o = 16; o; o >>= 1) mx = fmaxf(mx, __shfl_xor_sync(0xffffffffu, mx, o));
    if ((threadIdx.x & 31) == 0) red[threadIdx.x >> 5] = mx;
    __syncthreads();
    if (threadIdx.x == 0) {
        float m = red[0];
#pragma unroll
        for (int j = 1; j < 8; j++) m = fmaxf(m, red[j]);
        float sc = __fdiv_rn(fmaxf(m, EPSV), FP8MAX);
        s_scale = sc;
        g_Ws[row] = sc;
    }
    __syncthreads();
    const float sc = s_scale;

    uint32_t* oq = (uint32_t*)(g_Wq + (size_t)row * K_DIM);
#pragma unroll
    for (int i = 0; i < 4; i++) {
        uint16_t lo = cvt_e4m3x2(__fdiv_rn(v[i].x, sc), __fdiv_rn(v[i].y, sc));
        uint16_t hi = cvt_e4m3x2(__fdiv_rn(v[i].z, sc), __fdiv_rn(v[i].w, sc));
        oq[threadIdx.x + i * 256] = (uint32_t)lo | ((uint32_t)hi << 16);
    }
}

// ----------------------------- activation quant -----------------------------
__global__ void __launch_bounds__(256) aquant_kernel(const float* __restrict__ x) {
    const int row = blockIdx.x;
    const float4* xr = (const float4*)(x + (size_t)row * K_DIM);

    float a0[4], a1[4], a2[4], a3[4];
    float mx = 0.f;
#pragma unroll
    for (int i = 0; i < 4; i++) {
        float4 v = xr[threadIdx.x + i * 256];
        float r0 = fmaxf(v.x, 0.f), r1 = fmaxf(v.y, 0.f);
        float r2 = fmaxf(v.z, 0.f), r3 = fmaxf(v.w, 0.f);
        a0[i] = r0 * r0; a1[i] = r1 * r1; a2[i] = r2 * r2; a3[i] = r3 * r3;
        mx = fmaxf(mx, fmaxf(fmaxf(a0[i], a1[i]), fmaxf(a2[i], a3[i])));
    }
    __shared__ float red[8];
    __shared__ float s_scale;
#pragma unroll
    for (int o = 16; o; o >>= 1) mx = fmaxf(mx, __shfl_xor_sync(0xffffffffu, mx, o));
    if ((threadIdx.x & 31) == 0) red[threadIdx.x >> 5] = mx;
    __syncthreads();
    if (threadIdx.x == 0) {
        float m = red[0];
#pragma unroll
        for (int j = 1; j < 8; j++) m = fmaxf(m, red[j]);
        float sc = __fdiv_rn(fmaxf(m, EPSV), FP8MAX);
        s_scale = sc;
        g_Xs[row] = sc;
    }
    __syncthreads();
    const float sc = s_scale;

    uint32_t* oq = (uint32_t*)(g_Xq + (size_t)row * K_DIM);
#pragma unroll
    for (int i = 0; i < 4; i++) {
        float b0 = a0[i], b1 = a1[i], b2 = a2[i], b3 = a3[i];
        int i1 = 0; float m1 = b0;
        if (b1 > m1) { m1 = b1; i1 = 1; }
        if (b2 > m1) { m1 = b2; i1 = 2; }
        if (b3 > m1) { m1 = b3; i1 = 3; }
        float c0 = (i1 == 0) ? -1.f : b0;
        float c1 = (i1 == 1) ? -1.f : b1;
        float c2 = (i1 == 2) ? -1.f : b2;
        float c3 = (i1 == 3) ? -1.f : b3;
        int i2 = 0; float m2 = c0;
        if (c1 > m2) { m2 = c1; i2 = 1; }
        if (c2 > m2) { m2 = c2; i2 = 2; }
        if (c3 > m2) { m2 = c3; i2 = 3; }

        float q0 = (i1 == 0 || i2 == 0) ? __fdiv_rn(b0, sc) : 0.f;
        float q1 = (i1 == 1 || i2 == 1) ? __fdiv_rn(b1, sc) : 0.f;
        float q2 = (i1 == 2 || i2 == 2) ? __fdiv_rn(b2, sc) : 0.f;
        float q3 = (i1 == 3 || i2 == 3) ? __fdiv_rn(b3, sc) : 0.f;

        uint16_t lo = cvt_e4m3x2(q0, q1);
        uint16_t hi = cvt_e4m3x2(q2, q3);
        oq[threadIdx.x + i * 256] = (uint32_t)lo | ((uint32_t)hi << 16);
    }
}

// ----------------------------- dense fp8 GEMM (cross-barrier pipelined) -----
// 128x128 CTA tile, 8 warps (2x4), warp tile 64x32, BK=64, 6-stage cp.async
// ring, 2 CTAs/SM. Fragments software-pipelined across the kt barrier:
//   ldsm j1(kt) -> MMA j0(kt) -> wait<3>+bar -> cp(kt+5) -> ldsm j0(kt+1) -> MMA j1(kt)
// wait_group<3> guarantees stage kt+1 data resident before its early ldsm.
// 16B-chunk XOR swizzle: chunk' = chunk ^ ((row>>1)&3); chunk c = base ^ (c<<4).
__global__ void __launch_bounds__(256, 2) gemm_kernel(float* __restrict__ out) {
    extern __shared__ uint32_t sm[];
    const uint32_t sb = smem_u32(sm);
    const int tid = threadIdx.x;
    const int wid = tid >> 5;
    const int lane = tid & 31;
    const int gid = lane >> 2;
    const int t4 = lane & 3;
    const int wm = (wid >> 2) * 64;
    const int wn = (wid & 3) * 32;
    const int m0 = blockIdx.y * BM;
    const int n0 = blockIdx.x * BN;

    // ---- ldmatrix lane offsets (stage 0, chunk base) ----
    const int ar = lane & 15;
    const uint32_t swzA = ((uint32_t)ar >> 1) & 3;
    const uint32_t aAo = (uint32_t)(wm + ar) * 64 +
                         ((((uint32_t)lane >> 4) ^ swzA) << 4);
    const uint32_t swzB = ((uint32_t)lane >> 1) & 3;
    const uint32_t aBo = B_OFF + (uint32_t)(wn + lane) * 64 + (swzB << 4);

    // ---- producer mapping: thread -> (row lr, chunks 2h,2h+1) ----
    const int lr = tid >> 1;
    const int half = tid & 1;
    const uint8_t* pA = g_Xq + (size_t)(m0 + lr) * K_DIM + half * 32;
    const uint8_t* pB = g_Wq + (size_t)(n0 + lr) * K_DIM + half * 32;
    const uint32_t swzP = ((uint32_t)lr >> 1) & 3;
    const uint32_t sPo = (uint32_t)lr * 64 + ((((uint32_t)half * 2) ^ swzP) << 4);

    float acc[4][4][4];
#pragma unroll
    for (int i = 0; i < 4; i++)
#pragma unroll
        for (int j = 0; j < 4; j++)
#pragma unroll
            for (int c = 0; c < 4; c++) acc[i][j][c] = 0.f;

    // ---- prologue: fill STAGES-1 stages ----
#pragma unroll
    for (int s = 0; s < STAGES - 1; s++) {
        const uint32_t po = s * STG_BYTES;
        const size_t gk = (size_t)s * BK;
        cp16(sb + sPo + po, pA + gk);
        cp16(sb + (sPo ^ 0x10) + po, pA + gk + 16);
        cp16(sb + (sPo + B_OFF) + po, pB + gk);
        cp16(sb + ((sPo + B_OFF) ^ 0x10) + po, pB + gk + 16);
        cp_commit();
    }

    // frag buffers: slot0 = current j0, slot1 = current j1
    uint32_t a0[4][4], b0a[4], b0b[4];
    uint32_t a1[4][4], b1a[4], b1b[4];

    // ---- pre-loop: stage 0 ready after wait<3> (completed >= 2 stages) ----
    cp_wait<3>();
    __syncthreads();
#pragma unroll
    for (int mi = 0; mi < 4; mi++)
        ldsm4(a0[mi], sb + aAo + mi * 1024);
    ldsm4(b0a, sb + aBo);
    ldsm4(b0b, sb + (aBo ^ 0x10));

    // ---- main loop ----
#pragma unroll 1
    for (int kt = 0; kt < KT; kt++) {
        const uint32_t co = (kt % STAGES) * STG_BYTES;

        // ldsm j1 fragments of this kt (chunk +2 -> ^0x20)
#pragma unroll
        for (int mi = 0; mi < 4; mi++)
            ldsm4(a1[mi], sb + (aAo ^ 0x20) + co + mi * 1024);
        ldsm4(b1a, sb + (aBo ^ 0x20) + co);
        ldsm4(b1b, sb + (aBo ^ 0x30) + co);

        // MMA j0
#pragma unroll
        for (int mi = 0; mi < 4; mi++)
#pragma unroll
            for (int ni = 0; ni < 4; ni++)
                mma_fp8(acc[mi][ni], a0[mi], b0a[ni], b0b[ni]);

        // barrier: stage (kt+5)%6 == (kt-1)%6 becomes writable
        cp_wait<3>();
        __syncthreads();

        if (kt + STAGES - 1 < KT) {
            const uint32_t po = ((kt + STAGES - 1) % STAGES) * STG_BYTES;
            const size_t gk = (size_t)(kt + STAGES - 1) * BK;
            cp16(sb + sPo + po, pA + gk);
            cp16(sb + (sPo ^ 0x10) + po, pA + gk + 16);
            cp16(sb + (sPo + B_OFF) + po, pB + gk);
            cp16(sb + ((sPo + B_OFF) ^ 0x10) + po, pB + gk + 16);
        }
        cp_commit();

        // early ldsm: j0 fragments of NEXT kt (stage kt+1, data resident)
        if (kt + 1 < KT) {
            const uint32_t c2 = ((kt + 1) % STAGES) * STG_BYTES;
#pragma unroll
            for (int mi = 0; mi < 4; mi++)
                ldsm4(a0[mi], sb + aAo + c2 + mi * 1024);
            ldsm4(b0a, sb + aBo + c2);
            ldsm4(b0b, sb + (aBo ^ 0x10) + c2);
        }

        // MMA j1
#pragma unroll
        for (int mi = 0; mi < 4; mi++)
#pragma unroll
            for (int ni = 0; ni < 4; ni++)
                mma_fp8(acc[mi][ni], a1[mi], b1a[ni], b1b[ni]);
    }

    // ---- epilogue: rescale + store ----
#pragma unroll
    for (int mi = 0; mi < 4; mi++) {
        const int r0 = m0 + wm + mi * 16 + gid;
        const float xs0 = g_Xs[r0];
        const float xs1 = g_Xs[r0 + 8];
#pragma unroll
        for (int ni = 0; ni < 4; ni++) {
            const int c = n0 + wn + ni * 8 + t4 * 2;
            const float ws0 = g_Ws[c];
            const float ws1 = g_Ws[c + 1];
            float2 o0, o1;
            o0.x = acc[mi][ni][0] * xs0 * ws0;
            o0.y = acc[mi][ni][1] * xs0 * ws1;
            o1.x = acc[mi][ni][2] * xs1 * ws0;
            o1.y = acc[mi][ni][3] * xs1 * ws1;
            *(float2*)(out + (size_t)r0 * N_DIM + c) = o0;
            *(float2*)(out + (size_t)(r0 + 8) * N_DIM + c) = o1;
        }
    }
}

// ----------------------------- launch ---------------------------------------
extern "C" void kernel_launch(void* const* d_in, const int* in_sizes, int n_in,
                              void* d_out, int out_size) {
    const float* x = (const float*)d_in[0];   // [8192, 4096] f32
    const float* w = (const float*)d_in[1];   // [4096, 4096] f32
    float* out = (float*)d_out;               // [8192, 4096] f32
    (void)in_sizes; (void)n_in; (void)out_size;

    cudaFuncSetAttribute(gemm_kernel,
                         cudaFuncAttributeMaxDynamicSharedMemorySize, SMEM_BYTES);

    wquant_kernel<<<N_DIM, 256>>>(w);
    aquant_kernel<<<M_DIM, 256>>>(x);
    gemm_kernel<<<dim3(N_DIM / BN, M_DIM / BM), 256, SMEM_BYTES>>>(out);
}

// round 9
// speedup vs baseline: 1.2357x; 1.2357x over previous
#include <cuda_runtime.h>
#include <cstdint>

// ----------------------------- problem constants -----------------------------
#define M_DIM 8192
#define N_DIM 4096
#define K_DIM 4096
#define FP8MAX 448.0f
#define EPSV 1e-12f

// ----------------------------- GEMM tiling ----------------------------------
#define BM 128
#define BN 128
#define BK 64                   // original-K per stage (2 sparse k32 steps)
#define STAGES 6
#define KT (K_DIM / BK)         // 64

// per-stage smem: A_c 128x32 f16 = 8KB | B 128x64 f16 = 16KB | meta 1KB
#define AOFF 0
#define BOFF 8192
#define MOFF 24576
#define STG_BYTES 25600
#define SMEM_BYTES (STAGES * STG_BYTES)   // 153600

// ----------------------------- scratch (static device mem) ------------------
__device__ __align__(256) uint8_t  g_Xch[(size_t)M_DIM * K_DIM];      // compressed A, f16 (M x K/2)
__device__ __align__(256) uint8_t  g_Wh[(size_t)N_DIM * K_DIM * 2];   // B, f16 (N x K)
__device__ __align__(256) uint16_t g_Xm16[(size_t)M_DIM * (K_DIM / 16)];
__device__ __align__(256) uint32_t g_Xm32[(size_t)(M_DIM / 2) * (K_DIM / 16)];
__device__ __align__(16) float g_Xs[M_DIM];
__device__ __align__(16) float g_Ws[N_DIM];

// ----------------------------- PTX helpers ----------------------------------
__device__ __forceinline__ uint32_t smem_u32(const void* p) {
    uint32_t a;
    asm("{ .reg .u64 t; cvta.to.shared.u64 t, %1; cvt.u32.u64 %0, t; }"
        : "=r"(a) : "l"(p));
    return a;
}
__device__ __forceinline__ void cp16(uint32_t s, const void* g) {
    asm volatile("cp.async.cg.shared.global [%0], [%1], 16;" :: "r"(s), "l"(g));
}
__device__ __forceinline__ void cp_commit() {
    asm volatile("cp.async.commit_group;" ::: "memory");
}
template <int N>
__device__ __forceinline__ void cp_wait() {
    asm volatile("cp.async.wait_group %0;" :: "n"(N) : "memory");
}
__device__ __forceinline__ void ldsm4(uint32_t* r, uint32_t addr) {
    asm volatile("ldmatrix.sync.aligned.m8n8.x4.shared.b16 {%0,%1,%2,%3}, [%4];"
                 : "=r"(r[0]), "=r"(r[1]), "=r"(r[2]), "=r"(r[3]) : "r"(addr));
}
// sparse f16 mma: D(16x8) += A(16x32, 2:4 elementwise) * B(32x8), selector 0
__device__ __forceinline__ void mma_sp16(float* d, const uint32_t* a,
                                         const uint32_t* b, uint32_t e) {
    asm volatile(
        "mma.sp::ordered_metadata.sync.aligned.m16n8k32.row.col.f32.f16.f16.f32 "
        "{%0,%1,%2,%3}, {%4,%5,%6,%7}, {%8,%9,%10,%11}, {%0,%1,%2,%3}, %12, 0x0;"
        : "+f"(d[0]), "+f"(d[1]), "+f"(d[2]), "+f"(d[3])
        : "r"(a[0]), "r"(a[1]), "r"(a[2]), "r"(a[3]),
          "r"(b[0]), "r"(b[1]), "r"(b[2]), "r"(b[3]), "r"(e));
}
// pack two f32 -> e4m3x2 (lo in low byte), RN + satfinite
__device__ __forceinline__ uint16_t cvt_e4m3x2(float lo, float hi) {
    uint16_t r;
    asm volatile("cvt.rn.satfinite.e4m3x2.f32 %0, %1, %2;" : "=h"(r) : "f"(hi), "f"(lo));
    return r;
}
// e4m3 pair -> f16 pair (exact)
__device__ __forceinline__ uint32_t e4m3x2_to_f16x2(uint16_t v) {
    uint32_t r;
    asm("cvt.rn.f16x2.e4m3x2 %0, %1;" : "=r"(r) : "h"(v));
    return r;
}

// ----------------------------- weight quant (fp8-rounded f16 out) -----------
__global__ void __launch_bounds__(256) wquant_kernel(const float* __restrict__ w) {
    const int row = blockIdx.x;
    const int t = threadIdx.x;
    const float4* wr = (const float4*)(w + (size_t)row * K_DIM);

    float4 v[4];
    float mx = 0.f;
#pragma unroll
    for (int i = 0; i < 4; i++) {
        v[i] = wr[4 * t + i];
        mx = fmaxf(mx, fmaxf(fmaxf(fabsf(v[i].x), fabsf(v[i].y)),
                             fmaxf(fabsf(v[i].z), fabsf(v[i].w))));
    }
    __shared__ float red[8];
    __shared__ float s_scale;
#pragma unroll
    for (int o = 16; o; o >>= 1) mx = fmaxf(mx, __shfl_xor_sync(0xffffffffu, mx, o));
    if ((t & 31) == 0) red[t >> 5] = mx;
    __syncthreads();
    if (t == 0) {
        float m = red[0];
#pragma unroll
        for (int j = 1; j < 8; j++) m = fmaxf(m, red[j]);
        float sc = __fdiv_rn(fmaxf(m, EPSV), FP8MAX);
        s_scale = sc;
        g_Ws[row] = sc;
    }
    __syncthreads();
    const float sc = s_scale;

    float q[16];
#pragma unroll
    for (int i = 0; i < 4; i++) {
        q[4 * i + 0] = __fdiv_rn(v[i].x, sc);
        q[4 * i + 1] = __fdiv_rn(v[i].y, sc);
        q[4 * i + 2] = __fdiv_rn(v[i].z, sc);
        q[4 * i + 3] = __fdiv_rn(v[i].w, sc);
    }
    uint32_t h[8];
#pragma unroll
    for (int p = 0; p < 8; p++)
        h[p] = e4m3x2_to_f16x2(cvt_e4m3x2(q[2 * p], q[2 * p + 1]));
    uint4* orow = (uint4*)(g_Wh + (size_t)row * K_DIM * 2);
    orow[2 * t]     = make_uint4(h[0], h[1], h[2], h[3]);
    orow[2 * t + 1] = make_uint4(h[4], h[5], h[6], h[7]);
}

// ----------------------------- activation quant + 2:4 compress --------------
// one CTA per row; thread t = 16-elem window t. Outputs compressed f16 pairs
// (ascending index) + 16-bit metadata per window (group g -> bits[4g:4g+4)).
__global__ void __launch_bounds__(256) aquant_kernel(const float* __restrict__ x) {
    const int row = blockIdx.x;
    const int t = threadIdx.x;
    const float4* xr = (const float4*)(x + (size_t)row * K_DIM);

    float b[16];
    float mx = 0.f;
#pragma unroll
    for (int i = 0; i < 4; i++) {
        float4 v = xr[4 * t + i];
        float r0 = fmaxf(v.x, 0.f), r1 = fmaxf(v.y, 0.f);
        float r2 = fmaxf(v.z, 0.f), r3 = fmaxf(v.w, 0.f);
        b[4 * i + 0] = r0 * r0; b[4 * i + 1] = r1 * r1;
        b[4 * i + 2] = r2 * r2; b[4 * i + 3] = r3 * r3;
        mx = fmaxf(mx, fmaxf(fmaxf(b[4 * i], b[4 * i + 1]),
                             fmaxf(b[4 * i + 2], b[4 * i + 3])));
    }
    __shared__ float red[8];
    __shared__ float s_scale;
#pragma unroll
    for (int o = 16; o; o >>= 1) mx = fmaxf(mx, __shfl_xor_sync(0xffffffffu, mx, o));
    if ((t & 31) == 0) red[t >> 5] = mx;
    __syncthreads();
    if (t == 0) {
        float m = red[0];
#pragma unroll
        for (int j = 1; j < 8; j++) m = fmaxf(m, red[j]);
        float sc = __fdiv_rn(fmaxf(m, EPSV), FP8MAX);
        s_scale = sc;
        g_Xs[row] = sc;
    }
    __syncthreads();
    const float sc = s_scale;

    uint32_t h[4];
    uint32_t m16 = 0;
#pragma unroll
    for (int g = 0; g < 4; g++) {
        float b0 = b[4 * g], b1 = b[4 * g + 1], b2 = b[4 * g + 2], b3 = b[4 * g + 3];
        int i1 = 0; float m1 = b0;
        if (b1 > m1) { m1 = b1; i1 = 1; }
        if (b2 > m1) { m1 = b2; i1 = 2; }
        if (b3 > m1) { m1 = b3; i1 = 3; }
        float c0 = (i1 == 0) ? -1.f : b0;
        float c1 = (i1 == 1) ? -1.f : b1;
        float c2 = (i1 == 2) ? -1.f : b2;
        float c3 = (i1 == 3) ? -1.f : b3;
        int i2 = 0; float m2 = c0;
        if (c1 > m2) { m2 = c1; i2 = 1; }
        if (c2 > m2) { m2 = c2; i2 = 2; }
        if (c3 > m2) { m2 = c3; i2 = 3; }
        const int lo = min(i1, i2), hi = max(i1, i2);
        const float vlo = __fdiv_rn(b[4 * g + lo], sc);
        const float vhi = __fdiv_rn(b[4 * g + hi], sc);
        h[g] = e4m3x2_to_f16x2(cvt_e4m3x2(vlo, vhi));
        m16 |= (uint32_t)(lo | (hi << 2)) << (4 * g);
    }
    ((uint4*)(g_Xch + (size_t)row * (K_DIM / 2) * 2))[t] =
        make_uint4(h[0], h[1], h[2], h[3]);
    g_Xm16[(size_t)row * (K_DIM / 16) + t] = (uint16_t)m16;
}

// ----------------------------- metadata merge -------------------------------
// g_Xm32[(q*8+i)*256 + w] = m16(row 16q+i, w) | m16(row 16q+i+8, w) << 16
__global__ void __launch_bounds__(256) mmerge_kernel() {
    const int idx = blockIdx.x * 256 + threadIdx.x;
    const int q = idx >> 11;
    const int i = (idx >> 8) & 7;
    const int w = idx & 255;
    const uint32_t lo = g_Xm16[(size_t)(16 * q + i) * 256 + w];
    const uint32_t hi = g_Xm16[(size_t)(16 * q + i + 8) * 256 + w];
    g_Xm32[idx] = lo | (hi << 16);
}

// ----------------------------- 2:4 sparse f16 GEMM --------------------------
// 128x128 CTA, 512 threads, 16 warps (4x4), warp tile 32x32 (mi=2, ni=4).
// BK=64 orig-K per stage (2 sparse k32 steps), 6-stage cp.async ring, 1 CTA/SM.
// A rows 64B: chunk c -> c ^ ((row>>1)&3). B rows 128B: chunk c -> c ^ (row&7).
__global__ void __launch_bounds__(512, 1) gemm_kernel(float* __restrict__ out) {
    extern __shared__ uint32_t sm[];
    const uint32_t sb = smem_u32(sm);
    const int tid = threadIdx.x;
    const int wid = tid >> 5;
    const int lane = tid & 31;
    const int gid = lane >> 2;
    const int t4 = lane & 3;
    const int wm = (wid >> 2) * 32;
    const int wn = (wid & 3) * 32;
    const int m0 = blockIdx.y * BM;
    const int n0 = blockIdx.x * BN;

    // ---- ldmatrix lane address components ----
    const int ar = lane & 15;
    const uint32_t hiA = (uint32_t)lane >> 4;
    const uint32_t swzA = ((uint32_t)(wm + ar) >> 1) & 3;
    const uint32_t aA = (uint32_t)(wm + ar) * 64 + ((hiA ^ swzA) << 4);  // j=0; j=1: ^0x20
    const uint32_t brow = (uint32_t)(wn + lane);
    const uint32_t aB = BOFF + brow * 128 + ((brow & 7) << 4);           // chunk c: ^ (c<<4)
    // meta word select per lane
    const uint32_t wsel = (uint32_t)(t4 & 1);

    // ---- producers ----
    // A: 512 chunks (128 rows x 4): thread t -> row t>>2, chunk t&3
    const int arow = tid >> 2, ac = tid & 3;
    const uint8_t* gA = g_Xch + ((size_t)(m0 + arow) * (K_DIM / 2) + ac * 8) * 2;
    const uint32_t sA = sb + (uint32_t)arow * 64 +
                        (((uint32_t)ac ^ (((uint32_t)arow >> 1) & 3)) << 4);
    // B: 1024 chunks (128 rows x 8): thread t -> row t>>2, chunks {2(t&3), 2(t&3)+1}
    const int browp = tid >> 2, bc = (tid & 3) * 2;
    const uint8_t* gB = g_Wh + ((size_t)(n0 + browp) * K_DIM + bc * 8) * 2;
    const uint32_t sB0 = sb + BOFF + (uint32_t)browp * 128 +
                         (((uint32_t)bc ^ ((uint32_t)browp & 7)) << 4);
    // meta: threads 0-63 -> entry t (16B)
    const uint8_t* gM = (const uint8_t*)(g_Xm32 +
        ((size_t)((m0 >> 4) + (tid >> 3)) * 8 + (tid & 7)) * (K_DIM / 16));
    const uint32_t sM = sb + MOFF + (uint32_t)tid * 16;

    float acc[2][4][4];
#pragma unroll
    for (int i = 0; i < 2; i++)
#pragma unroll
        for (int j = 0; j < 4; j++)
#pragma unroll
            for (int c = 0; c < 4; c++) acc[i][j][c] = 0.f;

    // ---- prologue ----
#pragma unroll
    for (int s = 0; s < STAGES - 1; s++) {
        const uint32_t po = s * STG_BYTES;
        cp16(sA + po, gA + (size_t)s * 64);                  // 64B orig-window -> 32 f16 = 64B? no: 32 f16 = 64B per row-stage; this thread's 16B chunk at +s*64
        cp16(sB0 + po, gB + (size_t)s * 128);
        cp16((sB0 + po) ^ 0x10, gB + (size_t)s * 128 + 16);
        if (tid < 64) cp16(sM + po, gM + (size_t)s * 16);
        cp_commit();
    }

    // ---- main loop ----
#pragma unroll 1
    for (int kt = 0; kt < KT; kt++) {
        cp_wait<STAGES - 2>();
        __syncthreads();

        if (kt + STAGES - 1 < KT) {
            const uint32_t po = ((kt + STAGES - 1) % STAGES) * STG_BYTES;
            const size_t kk = (size_t)(kt + STAGES - 1);
            cp16(sA + po, gA + kk * 64);
            cp16(sB0 + po, gB + kk * 128);
            cp16((sB0 + po) ^ 0x10, gB + kk * 128 + 16);
            if (tid < 64) cp16(sM + po, gM + kk * 16);
        }
        cp_commit();

        const uint32_t co = (kt % STAGES) * STG_BYTES;

        // ---- bulk fragment loads ----
        uint32_t af[2][2][4];      // [j][mi]
        uint32_t bf[2][4][4];      // [j][kchunk][octet=ni]
        uint32_t em[2][2];         // [j][mi]
#pragma unroll
        for (int j = 0; j < 2; j++) {
            const uint32_t offj = (uint32_t)j << 5;          // ^0x20 toggles chunk pair
#pragma unroll
            for (int mi = 0; mi < 2; mi++)
                ldsm4(af[j][mi], sb + co + ((aA + (uint32_t)mi * 1024) ^ offj));
#pragma unroll
            for (int q = 0; q < 4; q++) {
                const uint32_t c = 4u * j + q;
                ldsm4(bf[j][q], sb + co + (aB ^ (c << 4)));
            }
#pragma unroll
            for (int mi = 0; mi < 2; mi++) {
                const uint32_t me = MOFF + ((((uint32_t)(wm >> 4) + mi) * 8 + gid) << 4)
                                    + ((2u * j + wsel) << 2);
                em[j][mi] = sm[(co + me) >> 2];
            }
        }

        // ---- 32 sparse MMAs ----
#pragma unroll
        for (int j = 0; j < 2; j++)
#pragma unroll
            for (int mi = 0; mi < 2; mi++)
#pragma unroll
                for (int ni = 0; ni < 4; ni++) {
                    uint32_t b[4] = { bf[j][0][ni], bf[j][1][ni],
                                      bf[j][2][ni], bf[j][3][ni] };
                    mma_sp16(acc[mi][ni], af[j][mi], b, em[j][mi]);
                }
    }

    // ---- epilogue: rescale + store ----
#pragma unroll
    for (int mi = 0; mi < 2; mi++) {
        const int r0 = m0 + wm + mi * 16 + gid;
        const float xs0 = g_Xs[r0];
        const float xs1 = g_Xs[r0 + 8];
#pragma unroll
        for (int ni = 0; ni < 4; ni++) {
            const int c = n0 + wn + ni * 8 + t4 * 2;
            const float ws0 = g_Ws[c];
            const float ws1 = g_Ws[c + 1];
            float2 o0, o1;
            o0.x = acc[mi][ni][0] * xs0 * ws0;
            o0.y = acc[mi][ni][1] * xs0 * ws1;
            o1.x = acc[mi][ni][2] * xs1 * ws0;
            o1.y = acc[mi][ni][3] * xs1 * ws1;
            *(float2*)(out + (size_t)r0 * N_DIM + c) = o0;
            *(float2*)(out + (size_t)(r0 + 8) * N_DIM + c) = o1;
        }
    }
}

// ----------------------------- launch ---------------------------------------
extern "C" void kernel_launch(void* const* d_in, const int* in_sizes, int n_in,
                              void* d_out, int out_size) {
    const float* x = (const float*)d_in[0];   // [8192, 4096] f32
    const float* w = (const float*)d_in[1];   // [4096, 4096] f32
    float* out = (float*)d_out;               // [8192, 4096] f32
    (void)in_sizes; (void)n_in; (void)out_size;

    cudaFuncSetAttribute(gemm_kernel,
                         cudaFuncAttributeMaxDynamicSharedMemorySize, SMEM_BYTES);

    wquant_kernel<<<N_DIM, 256>>>(w);
    aquant_kernel<<<M_DIM, 256>>>(x);
    mmerge_kernel<<<(M_DIM / 2) * (K_DIM / 16) / 256, 256>>>();
    gemm_kernel<<<dim3(N_DIM / BN, M_DIM / BM), 512, SMEM_BYTES>>>(out);
}

// round 10
// speedup vs baseline: 1.4327x; 1.1594x over previous
#include <cuda_runtime.h>
#include <cstdint>

// ----------------------------- problem constants -----------------------------
#define M_DIM 8192
#define N_DIM 4096
#define K_DIM 4096
#define FP8MAX 448.0f
#define EPSV 1e-12f

// ----------------------------- GEMM tiling ----------------------------------
#define BM 128
#define BN 128
#define BK 64                   // original-K per stage (2 sparse k32 steps)
#define STAGES 6
#define KT (K_DIM / BK)         // 64

// per-stage smem: A_c 128x32 f16 = 8KB | B 128x64 fp8 = 8KB | meta 1KB
#define AOFF 0
#define BOFF 8192
#define MOFF 16384
#define STG_BYTES 17408
#define SMEM_BYTES (STAGES * STG_BYTES)   // 104448

// ----------------------------- scratch (static device mem) ------------------
__device__ __align__(256) uint8_t  g_Xch[(size_t)M_DIM * K_DIM];      // compressed A, f16 (M x K/2)
__device__ __align__(256) uint8_t  g_Wq[(size_t)N_DIM * K_DIM];       // B, e4m3, 16B-window permuted
__device__ __align__(256) uint16_t g_Xm16[(size_t)M_DIM * (K_DIM / 16)];
__device__ __align__(256) uint32_t g_Xm32[(size_t)(M_DIM / 2) * (K_DIM / 16)];
__device__ __align__(16) float g_Xs[M_DIM];
__device__ __align__(16) float g_Ws[N_DIM];

// ----------------------------- PTX helpers ----------------------------------
__device__ __forceinline__ uint32_t smem_u32(const void* p) {
    uint32_t a;
    asm("{ .reg .u64 t; cvta.to.shared.u64 t, %1; cvt.u32.u64 %0, t; }"
        : "=r"(a) : "l"(p));
    return a;
}
__device__ __forceinline__ void cp16(uint32_t s, const void* g) {
    asm volatile("cp.async.cg.shared.global [%0], [%1], 16;" :: "r"(s), "l"(g));
}
__device__ __forceinline__ void cp_commit() {
    asm volatile("cp.async.commit_group;" ::: "memory");
}
template <int N>
__device__ __forceinline__ void cp_wait() {
    asm volatile("cp.async.wait_group %0;" :: "n"(N) : "memory");
}
__device__ __forceinline__ void ldsm4(uint32_t* r, uint32_t addr) {
    asm volatile("ldmatrix.sync.aligned.m8n8.x4.shared.b16 {%0,%1,%2,%3}, [%4];"
                 : "=r"(r[0]), "=r"(r[1]), "=r"(r[2]), "=r"(r[3]) : "r"(addr));
}
// sparse f16 mma: D(16x8) += A(16x32, 2:4 elementwise) * B(32x8), selector 0
__device__ __forceinline__ void mma_sp16(float* d, const uint32_t* a,
                                         const uint32_t* b, uint32_t e) {
    asm volatile(
        "mma.sp::ordered_metadata.sync.aligned.m16n8k32.row.col.f32.f16.f16.f32 "
        "{%0,%1,%2,%3}, {%4,%5,%6,%7}, {%8,%9,%10,%11}, {%0,%1,%2,%3}, %12, 0x0;"
        : "+f"(d[0]), "+f"(d[1]), "+f"(d[2]), "+f"(d[3])
        : "r"(a[0]), "r"(a[1]), "r"(a[2]), "r"(a[3]),
          "r"(b[0]), "r"(b[1]), "r"(b[2]), "r"(b[3]), "r"(e));
}
// pack two f32 -> e4m3x2 (lo in low byte), RN + satfinite
__device__ __forceinline__ uint16_t cvt_e4m3x2(float lo, float hi) {
    uint16_t r;
    asm volatile("cvt.rn.satfinite.e4m3x2.f32 %0, %1, %2;" : "=h"(r) : "f"(hi), "f"(lo));
    return r;
}
// e4m3 pair -> f16 pair (exact)
__device__ __forceinline__ uint32_t e4m3x2_to_f16x2(uint16_t v) {
    uint32_t r;
    asm("cvt.rn.f16x2.e4m3x2 %0, %1;" : "=r"(r) : "h"(v));
    return r;
}
// 4 packed e4m3 -> two f16x2 regs (lo = bytes 0,1; hi = bytes 2,3)
__device__ __forceinline__ void cvt8x4(uint32_t r, uint32_t& lo, uint32_t& hi) {
    asm("{ .reg .b16 l, h;\n\t"
        "mov.b32 {l, h}, %2;\n\t"
        "cvt.rn.f16x2.e4m3x2 %0, l;\n\t"
        "cvt.rn.f16x2.e4m3x2 %1, h; }"
        : "=r"(lo), "=r"(hi) : "r"(r));
}

// ----------------------------- weight quant (k-permuted fp8 out) ------------
// one CTA per row, one 16-elem k-window per thread. Within each window,
// stored[4t+0..3] = orig[2t, 2t+1, 2t+8, 2t+9]  (t = 0..3)
__global__ void __launch_bounds__(256) wquant_kernel(const float* __restrict__ w) {
    const int row = blockIdx.x;
    const int t = threadIdx.x;
    const float4* wr = (const float4*)(w + (size_t)row * K_DIM);

    float4 v[4];
    float mx = 0.f;
#pragma unroll
    for (int i = 0; i < 4; i++) {
        v[i] = wr[4 * t + i];
        mx = fmaxf(mx, fmaxf(fmaxf(fabsf(v[i].x), fabsf(v[i].y)),
                             fmaxf(fabsf(v[i].z), fabsf(v[i].w))));
    }
    __shared__ float red[8];
    __shared__ float s_scale;
#pragma unroll
    for (int o = 16; o; o >>= 1) mx = fmaxf(mx, __shfl_xor_sync(0xffffffffu, mx, o));
    if ((t & 31) == 0) red[t >> 5] = mx;
    __syncthreads();
    if (t == 0) {
        float m = red[0];
#pragma unroll
        for (int j = 1; j < 8; j++) m = fmaxf(m, red[j]);
        float sc = __fdiv_rn(fmaxf(m, EPSV), FP8MAX);
        s_scale = sc;
        g_Ws[row] = sc;
    }
    __syncthreads();
    const float sc = s_scale;

    float q[16];
#pragma unroll
    for (int i = 0; i < 4; i++) {
        q[4 * i + 0] = __fdiv_rn(v[i].x, sc);
        q[4 * i + 1] = __fdiv_rn(v[i].y, sc);
        q[4 * i + 2] = __fdiv_rn(v[i].z, sc);
        q[4 * i + 3] = __fdiv_rn(v[i].w, sc);
    }
    uint32_t ph[8];
#pragma unroll
    for (int p = 0; p < 8; p++) ph[p] = cvt_e4m3x2(q[2 * p], q[2 * p + 1]);
    uint4 o;
    o.x = ph[0] | (ph[4] << 16);
    o.y = ph[1] | (ph[5] << 16);
    o.z = ph[2] | (ph[6] << 16);
    o.w = ph[3] | (ph[7] << 16);
    ((uint4*)(g_Wq + (size_t)row * K_DIM))[t] = o;
}

// ----------------------------- activation quant + 2:4 compress --------------
// one CTA per row; thread t = 16-elem window t. Outputs compressed f16 pairs
// (ascending index) + 16-bit metadata per window (group g -> bits[4g:4g+4)).
__global__ void __launch_bounds__(256) aquant_kernel(const float* __restrict__ x) {
    const int row = blockIdx.x;
    const int t = threadIdx.x;
    const float4* xr = (const float4*)(x + (size_t)row * K_DIM);

    float b[16];
    float mx = 0.f;
#pragma unroll
    for (int i = 0; i < 4; i++) {
        float4 v = xr[4 * t + i];
        float r0 = fmaxf(v.x, 0.f), r1 = fmaxf(v.y, 0.f);
        float r2 = fmaxf(v.z, 0.f), r3 = fmaxf(v.w, 0.f);
        b[4 * i + 0] = r0 * r0; b[4 * i + 1] = r1 * r1;
        b[4 * i + 2] = r2 * r2; b[4 * i + 3] = r3 * r3;
        mx = fmaxf(mx, fmaxf(fmaxf(b[4 * i], b[4 * i + 1]),
                             fmaxf(b[4 * i + 2], b[4 * i + 3])));
    }
    __shared__ float red[8];
    __shared__ float s_scale;
#pragma unroll
    for (int o = 16; o; o >>= 1) mx = fmaxf(mx, __shfl_xor_sync(0xffffffffu, mx, o));
    if ((t & 31) == 0) red[t >> 5] = mx;
    __syncthreads();
    if (t == 0) {
        float m = red[0];
#pragma unroll
        for (int j = 1; j < 8; j++) m = fmaxf(m, red[j]);
        float sc = __fdiv_rn(fmaxf(m, EPSV), FP8MAX);
        s_scale = sc;
        g_Xs[row] = sc;
    }
    __syncthreads();
    const float sc = s_scale;

    uint32_t h[4];
    uint32_t m16 = 0;
#pragma unroll
    for (int g = 0; g < 4; g++) {
        float b0 = b[4 * g], b1 = b[4 * g + 1], b2 = b[4 * g + 2], b3 = b[4 * g + 3];
        int i1 = 0; float m1 = b0;
        if (b1 > m1) { m1 = b1; i1 = 1; }
        if (b2 > m1) { m1 = b2; i1 = 2; }
        if (b3 > m1) { m1 = b3; i1 = 3; }
        float c0 = (i1 == 0) ? -1.f : b0;
        float c1 = (i1 == 1) ? -1.f : b1;
        float c2 = (i1 == 2) ? -1.f : b2;
        float c3 = (i1 == 3) ? -1.f : b3;
        int i2 = 0; float m2 = c0;
        if (c1 > m2) { m2 = c1; i2 = 1; }
        if (c2 > m2) { m2 = c2; i2 = 2; }
        if (c3 > m2) { m2 = c3; i2 = 3; }
        const int lo = min(i1, i2), hi = max(i1, i2);
        const float vlo = __fdiv_rn(b[4 * g + lo], sc);
        const float vhi = __fdiv_rn(b[4 * g + hi], sc);
        h[g] = e4m3x2_to_f16x2(cvt_e4m3x2(vlo, vhi));
        m16 |= (uint32_t)(lo | (hi << 2)) << (4 * g);
    }
    ((uint4*)(g_Xch + (size_t)row * (K_DIM / 2) * 2))[t] =
        make_uint4(h[0], h[1], h[2], h[3]);
    g_Xm16[(size_t)row * (K_DIM / 16) + t] = (uint16_t)m16;
}

// ----------------------------- metadata merge -------------------------------
__global__ void __launch_bounds__(256) mmerge_kernel() {
    const int idx = blockIdx.x * 256 + threadIdx.x;
    const int q = idx >> 11;
    const int i = (idx >> 8) & 7;
    const int w = idx & 255;
    const uint32_t lo = g_Xm16[(size_t)(16 * q + i) * 256 + w];
    const uint32_t hi = g_Xm16[(size_t)(16 * q + i + 8) * 256 + w];
    g_Xm32[idx] = lo | (hi << 16);
}

// ----------------------------- 2:4 sparse f16 GEMM (B in fp8 smem) ----------
// 128x128 CTA, 512 threads, 16 warps (4x4), warp tile 32x32 (mi=2, ni=4).
// BK=64 orig-K per stage (2 sparse k32 steps), 6-stage cp.async ring, 1 CTA/SM.
// A rows 64B f16 (swizzle c^((row>>1)&3)); B rows 64B fp8 (same swizzle),
// converted fp8->f16 after ldsm (values identical thanks to 16B-window perm).
__global__ void __launch_bounds__(512, 1) gemm_kernel(float* __restrict__ out) {
    extern __shared__ uint32_t sm[];
    const uint32_t sb = smem_u32(sm);
    const int tid = threadIdx.x;
    const int wid = tid >> 5;
    const int lane = tid & 31;
    const int gid = lane >> 2;
    const int t4 = lane & 3;
    const int wm = (wid >> 2) * 32;
    const int wn = (wid & 3) * 32;
    const int m0 = blockIdx.y * BM;
    const int n0 = blockIdx.x * BN;

    // ---- ldmatrix lane address components ----
    const int ar = lane & 15;
    const uint32_t hiA = (uint32_t)lane >> 4;
    const uint32_t swzA = ((uint32_t)(wm + ar) >> 1) & 3;
    const uint32_t aA = (uint32_t)(wm + ar) * 64 + ((hiA ^ swzA) << 4);  // j: ^(j<<5)
    const uint32_t brow = (uint32_t)(wn + lane);
    const uint32_t swzB = (brow >> 1) & 3;
    const uint32_t aB = BOFF + brow * 64 + (swzB << 4);                  // chunk c: ^(c<<4)
    const uint32_t wsel = (uint32_t)(t4 & 1);

    // ---- producers ----
    // A: 512 chunks (128 rows x 4 x 16B): thread t -> row t>>2, chunk t&3
    const int arow = tid >> 2, ac = tid & 3;
    const uint8_t* gA = g_Xch + ((size_t)(m0 + arow) * (K_DIM / 2) + ac * 8) * 2;
    const uint32_t sA = sb + (uint32_t)arow * 64 +
                        (((uint32_t)ac ^ (((uint32_t)arow >> 1) & 3)) << 4);
    // B fp8: 512 chunks (128 rows x 4 x 16B): thread t -> row t>>2, chunk t&3
    const int browp = tid >> 2, bc = tid & 3;
    const uint8_t* gB = g_Wq + (size_t)(n0 + browp) * K_DIM + bc * 16;
    const uint32_t sB = sb + BOFF + (uint32_t)browp * 64 +
                        (((uint32_t)bc ^ (((uint32_t)browp >> 1) & 3)) << 4);
    // meta: threads 0-63 -> entry t (16B)
    const uint8_t* gM = (const uint8_t*)(g_Xm32 +
        ((size_t)((m0 >> 4) + (tid >> 3)) * 8 + (tid & 7)) * (K_DIM / 16));
    const uint32_t sM = sb + MOFF + (uint32_t)tid * 16;

    float acc[2][4][4];
#pragma unroll
    for (int i = 0; i < 2; i++)
#pragma unroll
        for (int j = 0; j < 4; j++)
#pragma unroll
            for (int c = 0; c < 4; c++) acc[i][j][c] = 0.f;

    // ---- prologue ----
#pragma unroll
    for (int s = 0; s < STAGES - 1; s++) {
        const uint32_t po = s * STG_BYTES;
        cp16(sA + po, gA + (size_t)s * 64);
        cp16(sB + po, gB + (size_t)s * 64);
        if (tid < 64) cp16(sM + po, gM + (size_t)s * 16);
        cp_commit();
    }

    // ---- main loop ----
#pragma unroll 1
    for (int kt = 0; kt < KT; kt++) {
        cp_wait<STAGES - 2>();
        __syncthreads();

        if (kt + STAGES - 1 < KT) {
            const uint32_t po = ((kt + STAGES - 1) % STAGES) * STG_BYTES;
            const size_t kk = (size_t)(kt + STAGES - 1);
            cp16(sA + po, gA + kk * 64);
            cp16(sB + po, gB + kk * 64);
            if (tid < 64) cp16(sM + po, gM + kk * 16);
        }
        cp_commit();

        const uint32_t co = (kt % STAGES) * STG_BYTES;

        // ---- bulk fragment loads ----
        uint32_t af[2][2][4];      // [j][mi] f16 A fragments
        uint32_t bf8[2][2][4];     // [j][k16-half p][ni] fp8 B fragments
        uint32_t em[2][2];         // [j][mi] metadata
#pragma unroll
        for (int j = 0; j < 2; j++) {
            const uint32_t offj = (uint32_t)j << 5;
#pragma unroll
            for (int mi = 0; mi < 2; mi++)
                ldsm4(af[j][mi], sb + co + ((aA + (uint32_t)mi * 1024) ^ offj));
#pragma unroll
            for (int p = 0; p < 2; p++) {
                const uint32_t c = 2u * j + p;
                ldsm4(bf8[j][p], sb + co + (aB ^ (c << 4)));
            }
#pragma unroll
            for (int mi = 0; mi < 2; mi++) {
                const uint32_t me = MOFF + ((((uint32_t)(wm >> 4) + mi) * 8 + gid) << 4)
                                    + ((2u * j + wsel) << 2);
                em[j][mi] = sm[(co + me) >> 2];
            }
        }

        // ---- 16 sparse MMAs (cvt B per (j,ni), reused across mi) ----
#pragma unroll
        for (int j = 0; j < 2; j++)
#pragma unroll
            for (int ni = 0; ni < 4; ni++) {
                uint32_t b[4];
                cvt8x4(bf8[j][0][ni], b[0], b[1]);
                cvt8x4(bf8[j][1][ni], b[2], b[3]);
#pragma unroll
                for (int mi = 0; mi < 2; mi++)
                    mma_sp16(acc[mi][ni], af[j][mi], b, em[j][mi]);
            }
    }

    // ---- epilogue: rescale + store ----
#pragma unroll
    for (int mi = 0; mi < 2; mi++) {
        const int r0 = m0 + wm + mi * 16 + gid;
        const float xs0 = g_Xs[r0];
        const float xs1 = g_Xs[r0 + 8];
#pragma unroll
        for (int ni = 0; ni < 4; ni++) {
            const int c = n0 + wn + ni * 8 + t4 * 2;
            const float ws0 = g_Ws[c];
            const float ws1 = g_Ws[c + 1];
            float2 o0, o1;
            o0.x = acc[mi][ni][0] * xs0 * ws0;
            o0.y = acc[mi][ni][1] * xs0 * ws1;
            o1.x = acc[mi][ni][2] * xs1 * ws0;
            o1.y = acc[mi][ni][3] * xs1 * ws1;
            *(float2*)(out + (size_t)r0 * N_DIM + c) = o0;
            *(float2*)(out + (size_t)(r0 + 8) * N_DIM + c) = o1;
        }
    }
}

// ----------------------------- launch ---------------------------------------
extern "C" void kernel_launch(void* const* d_in, const int* in_sizes, int n_in,
                              void* d_out, int out_size) {
    const float* x = (const float*)d_in[0];   // [8192, 4096] f32
    const float* w = (const float*)d_in[1];   // [4096, 4096] f32
    float* out = (float*)d_out;               // [8192, 4096] f32
    (void)in_sizes; (void)n_in; (void)out_size;

    cudaFuncSetAttribute(gemm_kernel,
                         cudaFuncAttributeMaxDynamicSharedMemorySize, SMEM_BYTES);

    wquant_kernel<<<N_DIM, 256>>>(w);
    aquant_kernel<<<M_DIM, 256>>>(x);
    mmerge_kernel<<<(M_DIM / 2) * (K_DIM / 16) / 256, 256>>>();
    gemm_kernel<<<dim3(N_DIM / BN, M_DIM / BM), 512, SMEM_BYTES>>>(out);
}